// round 15
// baseline (speedup 1.0000x reference)
#include <cuda_runtime.h>
#include <cuda_fp16.h>

#define BB 512
#define TT 128
#define FF 256
#define HH 384
#define LL 3
#define KW 10
#define LAB 25
#define GATES 1542
#define HID 64
#define CONVK (HH * KW)   // 3840
#define NPAD 1664         // 13*128
// permuted gate layout: col 4e+q (q: 0=f,1=i,2=o,3=c) for e in [0,384); cols 1536..1541 = fm/im raw

// ---------------- device scratch ----------------
__device__ __align__(16) int   g_perm[BB];
__device__ __align__(16) int   g_vlen[BB];
__device__ __align__(16) int   g_nact[TT];
__device__ float g_pre[(size_t)TT * BB * NPAD];               // 436 MB
__device__ __align__(16) float g_hbuf[2][BB * HH];            // ping-pong h state
__device__ __align__(16) float g_c[BB * HH];
__device__ __align__(16) float g_hist[(size_t)TT * BB * HH];  // 100 MB
__device__ __align__(16) float g_dish[TT * BB];
__device__ __align__(16) float g_convT[CONVK * HH];
__device__ __align__(16) float g_lh[BB * CONVK];
__device__ __align__(16) float g_theme[BB * HH];
__device__ __align__(16) float g_conv[BB * HH];
// fp16 split weights, transposed to [n][k], columns PERMUTED per layout above
__device__ __align__(16) __half g_BkwH[2][NPAD * FF];         // hi, lo
__device__ __align__(16) __half g_BrwH[2][NPAD * HH];
__device__ __align__(16) float g_bias0[NPAD];
__device__ __align__(16) float g_biasT[NPAD];

__device__ __forceinline__ float sigm(float x) { return 1.f / (1.f + expf(-x)); }

__device__ __forceinline__ void split2(float x, float y, unsigned& hi, unsigned& lo) {
    __half hx = __float2half_rn(x), hy = __float2half_rn(y);
    __half lx = __float2half_rn(x - __half2float(hx));
    __half ly = __float2half_rn(y - __half2float(hy));
    hi = ((unsigned)__half_as_ushort(hy) << 16) | (unsigned)__half_as_ushort(hx);
    lo = ((unsigned)__half_as_ushort(ly) << 16) | (unsigned)__half_as_ushort(lx);
}

#define MMA_F16(cc, a, b0, b1)                                                  \
    asm volatile("mma.sync.aligned.m16n8k16.row.col.f32.f16.f16.f32 "           \
        "{%0,%1,%2,%3}, {%4,%5,%6,%7}, {%8,%9}, {%0,%1,%2,%3};"                 \
        : "+f"((cc)[0]), "+f"((cc)[1]), "+f"((cc)[2]), "+f"((cc)[3])            \
        : "r"((a)[0]), "r"((a)[1]), "r"((a)[2]), "r"((a)[3]),                   \
          "r"(b0), "r"(b1))

// ---------------- setup ----------------
__global__ void k_setup(const int* __restrict__ vlen) {
    int cnt[129];
    for (int v = 0; v <= 128; v++) cnt[v] = 0;
    for (int b = 0; b < BB; b++) cnt[vlen[b]]++;
    int cur[129];
    int off = 0;
    for (int v = 128; v >= 1; v--) { cur[v] = off; off += cnt[v]; }
    for (int b = 0; b < BB; b++) {
        int v = vlen[b];
        int p = cur[v]++;
        g_perm[p] = b;
        g_vlen[p] = v;
    }
    int suf = 0;
    for (int t = TT - 1; t >= 0; t--) { suf += cnt[t + 1]; g_nact[t] = suf; }
}

__global__ void k_zero() {
    int i = blockIdx.x * blockDim.x + threadIdx.x;
    if (i < BB * HH) {
        g_hbuf[0][i] = 0.f;
        g_hbuf[1][i] = 0.f;
        g_c[i] = 0.f;
    }
}

__global__ void k_convT(const float* __restrict__ cw) {
    int i = blockIdx.x * blockDim.x + threadIdx.x;
    if (i >= HH * HH * KW) return;
    int k  = i % KW;
    int hh = (i / KW) % HH;
    int o  = i / (KW * HH);
    g_convT[(hh * KW + k) * HH + o] = cw[i];
}

// ---------------- prep: permute + split + transpose weights ----------------
__global__ void k_prep(const float* __restrict__ kw, const float* __restrict__ kb,
                       const float* __restrict__ rw, const float* __restrict__ rb) {
    int n = blockIdx.x;
    int k = threadIdx.x;
    int src;
    bool v;
    if (n < 1536)      { src = 6 + (n & 3) * HH + (n >> 2); v = true; }
    else if (n < 1542) { src = n - 1536; v = true; }
    else               { src = 0; v = false; }
    if (k < FF) {
        float w = v ? kw[k * GATES + src] : 0.f;
        __half hi = __float2half_rn(w);
        g_BkwH[0][n * FF + k] = hi;
        g_BkwH[1][n * FF + k] = __float2half_rn(w - __half2float(hi));
    }
    if (k < HH) {
        float w = v ? rw[k * GATES + src] : 0.f;
        __half hi = __float2half_rn(w);
        g_BrwH[0][n * HH + k] = hi;
        g_BrwH[1][n * HH + k] = __float2half_rn(w - __half2float(hi));
    }
    if (k == 0) {
        float b0 = v ? (kb[src] + rb[src]) : 0.f;
        float bT = b0 + (v ? (kw[FF * GATES + src] + rw[HH * GATES + src]) : 0.f);
        g_bias0[n] = b0;
        g_biasT[n] = bT;
    }
}

// ---------------- fp16 pre-GEMM: 64(t) x 128(n) tiles, vlen skip (R11-proven) ----------------
__global__ __launch_bounds__(256) void k_gemm_pre_fp16(const float* __restrict__ X) {
    __shared__ __half SA[2][64 * 24];    // [hi/lo], row stride 24 fp16
    __shared__ __half SB[2][128 * 24];

    int p  = blockIdx.y >> 1;
    int t0 = (blockIdx.y & 1) * 64;
    if (t0 >= g_vlen[p]) return;
    int n0 = blockIdx.x * 128;
    int tid = threadIdx.x;
    int lane = tid & 31, wid = tid >> 5;
    int wm = wid >> 2, wn = wid & 3;
    int g = lane >> 2, tq = lane & 3;
    const float* A = X + (size_t)g_perm[p] * (TT * FF) + (size_t)t0 * FF;

    int am = tid >> 2, ak = (tid & 3) * 4;
    int bm = tid >> 1, bk = (tid & 1) * 8;

    float c[2][4][4] = {};

    float4 va;
    uint4 vbh, vbl;
    va  = *(const float4*)(A + am * FF + ak);
    vbh = *(const uint4*)(&g_BkwH[0][(n0 + bm) * FF + bk]);
    vbl = *(const uint4*)(&g_BkwH[1][(n0 + bm) * FF + bk]);

    const int nK = FF / 16;  // 16
    for (int kt = 0; kt < nK; kt++) {
        {
            unsigned h0, l0, h1, l1;
            split2(va.x, va.y, h0, l0);
            split2(va.z, va.w, h1, l1);
            *(uint2*)&SA[0][am * 24 + ak] = make_uint2(h0, h1);
            *(uint2*)&SA[1][am * 24 + ak] = make_uint2(l0, l1);
            *(uint4*)&SB[0][bm * 24 + bk] = vbh;
            *(uint4*)&SB[1][bm * 24 + bk] = vbl;
        }
        __syncthreads();
        if (kt + 1 < nK) {
            int k0 = (kt + 1) * 16;
            va  = *(const float4*)(A + am * FF + k0 + ak);
            vbh = *(const uint4*)(&g_BkwH[0][(n0 + bm) * FF + k0 + bk]);
            vbl = *(const uint4*)(&g_BkwH[1][(n0 + bm) * FF + k0 + bk]);
        }

        const unsigned* sah = (const unsigned*)SA[0];
        const unsigned* sal = (const unsigned*)SA[1];
        const unsigned* sbh = (const unsigned*)SB[0];
        const unsigned* sbl = (const unsigned*)SB[1];

        unsigned ah[2][4], al[2][4];
        #pragma unroll
        for (int mf = 0; mf < 2; mf++) {
            int r = wm * 32 + mf * 16 + g;
            ah[mf][0] = sah[r * 12 + tq];
            ah[mf][1] = sah[(r + 8) * 12 + tq];
            ah[mf][2] = sah[r * 12 + tq + 4];
            ah[mf][3] = sah[(r + 8) * 12 + tq + 4];
            al[mf][0] = sal[r * 12 + tq];
            al[mf][1] = sal[(r + 8) * 12 + tq];
            al[mf][2] = sal[r * 12 + tq + 4];
            al[mf][3] = sal[(r + 8) * 12 + tq + 4];
        }
        #pragma unroll
        for (int nf = 0; nf < 4; nf++) {
            int nn = wn * 32 + nf * 8 + g;
            unsigned bh0 = sbh[nn * 12 + tq], bh1 = sbh[nn * 12 + tq + 4];
            unsigned bl0 = sbl[nn * 12 + tq], bl1 = sbl[nn * 12 + tq + 4];
            #pragma unroll
            for (int mf = 0; mf < 2; mf++) {
                MMA_F16(c[mf][nf], ah[mf], bh0, bh1);
                MMA_F16(c[mf][nf], ah[mf], bl0, bl1);
                MMA_F16(c[mf][nf], al[mf], bh0, bh1);
            }
        }
        __syncthreads();
    }

    #pragma unroll
    for (int mf = 0; mf < 2; mf++) {
        int r0 = wm * 32 + mf * 16 + g;
        int r1 = r0 + 8;
        int ta = t0 + r0, tb = t0 + r1;
        #pragma unroll
        for (int nf = 0; nf < 4; nf++) {
            int col = n0 + wn * 32 + nf * 8 + 2 * tq;
            float b0a = (ta == 0) ? g_bias0[col] : g_biasT[col];
            float b0b = (ta == 0) ? g_bias0[col + 1] : g_biasT[col + 1];
            float2 v;
            v.x = c[mf][nf][0] + b0a;
            v.y = c[mf][nf][1] + b0b;
            *(float2*)&g_pre[((size_t)ta * BB + p) * NPAD + col] = v;
            v.x = c[mf][nf][2] + g_biasT[col];
            v.y = c[mf][nf][3] + g_biasT[col + 1];
            *(float2*)&g_pre[((size_t)tb * BB + p) * NPAD + col] = v;
        }
    }
}

// ---------------- fused step: K split across warps (wk), double-buffered ----------------
// grid (24, 16), 256 thr, 8 warps (wk, wm, wn). Each wk-half owns 12 of 24 k-tiles;
// partial accumulators reduced through smem at the end. Reads g_hbuf[t&1], writes
// g_hbuf[(t+1)&1] — no cross-block hazards.
__global__ __launch_bounds__(256) void k_step(int t) {
    __shared__ __half SA[2][2][2][32 * 24];   // [stage][khalf][hi/lo]
    __shared__ __half SB[2][2][2][72 * 24];
    __shared__ float SR[4][32][20];           // wk=1 partials: 16 c + 4 csp
    __shared__ float SX[32 * 76];
    __shared__ float sfm[32], sim[32];

    int na = g_nact[t];
    int m0 = blockIdx.y * 32;
    if (m0 >= na) return;
    int n0 = blockIdx.x * 64;
    int e0 = blockIdx.x * 16;
    int tid = threadIdx.x;
    int lane = tid & 31, wid = tid >> 5;
    int wk = wid >> 2;
    int wm = (wid >> 1) & 1, wn = wid & 1;
    int g = lane >> 2, tq = lane & 3;

    int t7 = tid & 127;
    int kh = tid >> 7;                       // loader's k-half
    int am = t7 >> 2, ak = (t7 & 3) * 4;
    int bm = t7 >> 1, bk = (t7 & 1) * 8;
    int kbase = kh * 192;                    // 12 k-tiles * 16
    const float* A = g_hbuf[t & 1] + m0 * HH;
    float* Hout = g_hbuf[(t + 1) & 1];

    float c[4][4] = {};
    float csp[4] = {};

    float4 va;
    uint4 vbh, vbl, vsh, vsl;

    // prologue: each 128-thread group loads k-tile 0 of its half into stage 0
    va  = *(const float4*)(A + am * HH + kbase + ak);
    vbh = *(const uint4*)(&g_BrwH[0][(n0 + bm) * HH + kbase + bk]);
    vbl = *(const uint4*)(&g_BrwH[1][(n0 + bm) * HH + kbase + bk]);
    if (t7 < 16) {
        vsh = *(const uint4*)(&g_BrwH[0][(1536 + bm) * HH + kbase + bk]);
        vsl = *(const uint4*)(&g_BrwH[1][(1536 + bm) * HH + kbase + bk]);
    }
    {
        unsigned h0, l0, h1, l1;
        split2(va.x, va.y, h0, l0);
        split2(va.z, va.w, h1, l1);
        *(uint2*)&SA[0][kh][0][am * 24 + ak] = make_uint2(h0, h1);
        *(uint2*)&SA[0][kh][1][am * 24 + ak] = make_uint2(l0, l1);
        *(uint4*)&SB[0][kh][0][bm * 24 + bk] = vbh;
        *(uint4*)&SB[0][kh][1][bm * 24 + bk] = vbl;
        if (t7 < 16) {
            *(uint4*)&SB[0][kh][0][(64 + bm) * 24 + bk] = vsh;
            *(uint4*)&SB[0][kh][1][(64 + bm) * 24 + bk] = vsl;
        }
    }
    __syncthreads();

    const int nIT = 12;
    for (int it = 0; it < nIT; it++) {
        int cur = it & 1;
        bool more = (it + 1 < nIT);
        if (more) {
            int k0 = kbase + (it + 1) * 16;
            va  = *(const float4*)(A + am * HH + k0 + ak);
            vbh = *(const uint4*)(&g_BrwH[0][(n0 + bm) * HH + k0 + bk]);
            vbl = *(const uint4*)(&g_BrwH[1][(n0 + bm) * HH + k0 + bk]);
            if (t7 < 16) {
                vsh = *(const uint4*)(&g_BrwH[0][(1536 + bm) * HH + k0 + bk]);
                vsl = *(const uint4*)(&g_BrwH[1][(1536 + bm) * HH + k0 + bk]);
            }
        }

        const unsigned* sah = (const unsigned*)SA[cur][wk][0];
        const unsigned* sal = (const unsigned*)SA[cur][wk][1];
        const unsigned* sbh = (const unsigned*)SB[cur][wk][0];
        const unsigned* sbl = (const unsigned*)SB[cur][wk][1];

        unsigned ah[4], al[4];
        int r = wm * 16 + g;
        ah[0] = sah[r * 12 + tq];
        ah[1] = sah[(r + 8) * 12 + tq];
        ah[2] = sah[r * 12 + tq + 4];
        ah[3] = sah[(r + 8) * 12 + tq + 4];
        al[0] = sal[r * 12 + tq];
        al[1] = sal[(r + 8) * 12 + tq];
        al[2] = sal[r * 12 + tq + 4];
        al[3] = sal[(r + 8) * 12 + tq + 4];

        #pragma unroll
        for (int nf = 0; nf < 4; nf++) {
            int nn = wn * 32 + nf * 8 + g;
            unsigned bh0 = sbh[nn * 12 + tq], bh1 = sbh[nn * 12 + tq + 4];
            unsigned bl0 = sbl[nn * 12 + tq], bl1 = sbl[nn * 12 + tq + 4];
            MMA_F16(c[nf], ah, bh0, bh1);
            MMA_F16(c[nf], ah, bl0, bl1);
            MMA_F16(c[nf], al, bh0, bh1);
        }
        if (wn == 0) {
            int nn = 64 + g;
            unsigned bh0 = sbh[nn * 12 + tq], bh1 = sbh[nn * 12 + tq + 4];
            unsigned bl0 = sbl[nn * 12 + tq], bl1 = sbl[nn * 12 + tq + 4];
            MMA_F16(csp, ah, bh0, bh1);
            MMA_F16(csp, ah, bl0, bl1);
            MMA_F16(csp, al, bh0, bh1);
        }

        if (more) {
            int nxt = cur ^ 1;
            unsigned h0, l0, h1, l1;
            split2(va.x, va.y, h0, l0);
            split2(va.z, va.w, h1, l1);
            *(uint2*)&SA[nxt][kh][0][am * 24 + ak] = make_uint2(h0, h1);
            *(uint2*)&SA[nxt][kh][1][am * 24 + ak] = make_uint2(l0, l1);
            *(uint4*)&SB[nxt][kh][0][bm * 24 + bk] = vbh;
            *(uint4*)&SB[nxt][kh][1][bm * 24 + bk] = vbl;
            if (t7 < 16) {
                *(uint4*)&SB[nxt][kh][0][(64 + bm) * 24 + bk] = vsh;
                *(uint4*)&SB[nxt][kh][1][(64 + bm) * 24 + bk] = vsl;
            }
        }
        __syncthreads();
    }

    // cross-wk reduction: wk=1 dumps partials, wk=0 accumulates
    if (wk == 1) {
        int w = wm * 2 + wn;
        #pragma unroll
        for (int nf = 0; nf < 4; nf++)
            #pragma unroll
            for (int q = 0; q < 4; q++)
                SR[w][lane][nf * 4 + q] = c[nf][q];
        if (wn == 0) {
            #pragma unroll
            for (int q = 0; q < 4; q++) SR[w][lane][16 + q] = csp[q];
        }
    }
    __syncthreads();

    if (wk == 0) {
        int w = wm * 2 + wn;
        #pragma unroll
        for (int nf = 0; nf < 4; nf++)
            #pragma unroll
            for (int q = 0; q < 4; q++)
                c[nf][q] += SR[w][lane][nf * 4 + q];
        if (wn == 0) {
            #pragma unroll
            for (int q = 0; q < 4; q++) csp[q] += SR[w][lane][16 + q];
        }

        // write xo tile (acc + pre) to smem
        const float* pre = g_pre + (size_t)t * BB * NPAD;
        int r0 = wm * 16 + g;
        int r1 = r0 + 8;
        #pragma unroll
        for (int nf = 0; nf < 4; nf++) {
            int cc = wn * 32 + nf * 8 + 2 * tq;
            const float* p0 = &pre[(size_t)(m0 + r0) * NPAD + n0 + cc];
            const float* p1 = &pre[(size_t)(m0 + r1) * NPAD + n0 + cc];
            SX[r0 * 76 + cc]     = c[nf][0] + p0[0];
            SX[r0 * 76 + cc + 1] = c[nf][1] + p0[1];
            SX[r1 * 76 + cc]     = c[nf][2] + p1[0];
            SX[r1 * 76 + cc + 1] = c[nf][3] + p1[1];
        }
        if (wn == 0) {
            int cc = 64 + 2 * tq;
            const float* p0 = &pre[(size_t)(m0 + r0) * NPAD + 1536 + 2 * tq];
            const float* p1 = &pre[(size_t)(m0 + r1) * NPAD + 1536 + 2 * tq];
            SX[r0 * 76 + cc]     = csp[0] + p0[0];
            SX[r0 * 76 + cc + 1] = csp[1] + p0[1];
            SX[r1 * 76 + cc]     = csp[2] + p1[0];
            SX[r1 * 76 + cc + 1] = csp[3] + p1[1];
        }
    }
    __syncthreads();

    // per-row cumax softmax from special cols (threads 0..31)
    if (tid < 32) {
        int row = tid;
        float a0 = SX[row * 76 + 64], a1 = SX[row * 76 + 65], a2 = SX[row * 76 + 66];
        float m = fmaxf(a0, fmaxf(a1, a2));
        float e0v = expf(a0 - m), e1v = expf(a1 - m), e2v = expf(a2 - m);
        float inv = 1.f / (e0v + e1v + e2v);
        float fm0 = e0v * inv, fm1 = (e0v + e1v) * inv, fm2 = (e0v + e1v + e2v) * inv;
        float b0 = SX[row * 76 + 67], b1 = SX[row * 76 + 68], b2 = SX[row * 76 + 69];
        float mb = fmaxf(b0, fmaxf(b1, b2));
        float f0 = expf(b0 - mb), f1 = expf(b1 - mb), f2 = expf(b2 - mb);
        float invb = 1.f / (f0 + f1 + f2);
        float im0 = (f0 + f1 + f2) * invb, im1 = (f1 + f2) * invb, im2 = f2 * invb;
        int l = e0 >> 7;
        sfm[row] = (l == 0) ? fm0 : ((l == 1) ? fm1 : fm2);
        sim[row] = (l == 0) ? im0 : ((l == 1) ? im1 : im2);
        if (blockIdx.x == 0)
            g_dish[t * BB + m0 + row] = 1.f - (fm0 + fm1 + fm2) * (1.f / 3.f);
    }
    __syncthreads();

    // in-block pointwise for 32 rows x 16 elements (256 threads, 2 iters)
    #pragma unroll
    for (int i = 0; i < 2; i++) {
        int idx = tid + i * 256;
        int row = idx >> 4;
        int le = idx & 15;
        int ge = e0 + le;
        int p = m0 + row;
        const float* x4 = &SX[row * 76 + le * 4];
        float fg = sigm(x4[0]);
        float ig = sigm(x4[1]);
        float og = sigm(x4[2]);
        float ci = tanhf(x4[3]);
        float fm = sfm[row], im = sim[row], ov = fm * im;
        float cl = g_c[p * HH + ge];
        float cn = ov * (fg * cl + ig * ci) + (fm - ov) * cl + (im - ov) * ci;
        float hn = og * tanhf(cn);
        g_c[p * HH + ge] = cn;
        Hout[p * HH + ge] = hn;
        g_hist[((size_t)t * BB + p) * HH + ge] = hn;
    }
}

// ---------------- batched epilogue ----------------
__global__ void k_fin1(const float* __restrict__ scale_w, const float* __restrict__ scale_b,
                       const float* __restrict__ rescale_w, const float* __restrict__ rescale_b) {
    int p = blockIdx.x;
    int tl = g_vlen[p] - 1;
    int tid = threadIdx.x;
    __shared__ float s_ldis[KW];
    __shared__ float s_th[HH];
    __shared__ float s_r1[HID];

    if (tid == 0) {
        float buf[KW];
        float cs = 0.f;
        #pragma unroll
        for (int k = 0; k < KW; k++) {
            int s = tl - (KW - 1) + k;
            cs += (s >= 0) ? g_dish[s * BB + p] : 0.f;
            buf[k] = cs;
        }
        float m = buf[0];
        #pragma unroll
        for (int k = 1; k < KW; k++) m = fmaxf(m, buf[k]);
        float sum = 0.f;
        #pragma unroll
        for (int k = 0; k < KW; k++) { buf[k] = expf(buf[k] - m); sum += buf[k]; }
        float invs = 1.f / sum;
        #pragma unroll
        for (int k = 0; k < KW; k++) s_ldis[k] = buf[k] * invs;
    }
    __syncthreads();

    for (int e = tid; e < HH; e += 256) {
        float tp = 0.f;
        #pragma unroll
        for (int k = 0; k < KW; k++) {
            int s = tl - (KW - 1) + k;
            float hv = (s >= 0) ? g_hist[((size_t)s * BB + p) * HH + e] : 0.f;
            float lv = hv * s_ldis[k];
            g_lh[(size_t)p * CONVK + e * KW + k] = lv;
            tp += lv;
        }
        s_th[e] = tp * (1.f / KW);
    }
    __syncthreads();

    if (tid < HID) {
        float a = scale_b[tid];
        for (int h = 0; h < HH; h++) a += s_th[h] * scale_w[h * HID + tid];
        s_r1[tid] = fmaxf(a, 0.f);
    }
    __syncthreads();

    for (int e = tid; e < HH; e += 256) {
        float th2 = rescale_b[e];
        #pragma unroll 8
        for (int j = 0; j < HID; j++) th2 += s_r1[j] * rescale_w[j * HH + e];
        g_theme[p * HH + e] = sigm(th2);
    }
}

// fin2: conv GEMM  g_conv[512,384] = g_lh[512,3840] @ g_convT[3840,384]
__global__ void k_fin2() {
    __shared__ float As[16][68];
    __shared__ float Bs[16][68];
    int m0 = blockIdx.y * 64;
    int nb = blockIdx.x * 64;
    int tid  = threadIdx.x;
    int ty   = tid >> 4, tx = tid & 15;
    int arow = tid >> 2, akk = (tid & 3) << 2;
    int bk   = tid >> 4, bn  = (tid & 15) << 2;
    float acc[4][4] = {};
    const float* A = g_lh + (size_t)m0 * CONVK;

    float4 a_nxt = *(const float4*)(A + (size_t)arow * CONVK + akk);
    float4 b_nxt = *(const float4*)(g_convT + bk * HH + nb + bn);

    for (int k0 = 0; k0 < CONVK; k0 += 16) {
        As[akk + 0][arow] = a_nxt.x; As[akk + 1][arow] = a_nxt.y;
        As[akk + 2][arow] = a_nxt.z; As[akk + 3][arow] = a_nxt.w;
        *(float4*)&Bs[bk][bn] = b_nxt;
        __syncthreads();
        if (k0 + 16 < CONVK) {
            a_nxt = *(const float4*)(A + (size_t)arow * CONVK + k0 + 16 + akk);
            b_nxt = *(const float4*)(g_convT + (k0 + 16 + bk) * HH + nb + bn);
        }
        #pragma unroll
        for (int k = 0; k < 16; k++) {
            float4 a = *(const float4*)&As[k][ty * 4];
            float4 b = *(const float4*)&Bs[k][tx * 4];
            float avr[4] = {a.x, a.y, a.z, a.w};
            float bvr[4] = {b.x, b.y, b.z, b.w};
            #pragma unroll
            for (int i = 0; i < 4; i++)
                #pragma unroll
                for (int j = 0; j < 4; j++) acc[i][j] += avr[i] * bvr[j];
        }
        __syncthreads();
    }
    #pragma unroll
    for (int i = 0; i < 4; i++)
        #pragma unroll
        for (int j = 0; j < 4; j++)
            g_conv[(m0 + ty * 4 + i) * HH + nb + tx * 4 + j] = acc[i][j];
}

__global__ void k_fin3(const float* __restrict__ conv_b, const float* __restrict__ out_w,
                       const float* __restrict__ out_b, float* __restrict__ out) {
    int p = blockIdx.x;
    int tid = threadIdx.x;
    int tl = g_vlen[p] - 1;
    __shared__ float s_rnn[HH];
    s_rnn[tid] = g_theme[p * HH + tid] * (g_conv[p * HH + tid] + conv_b[tid])
               + g_hist[((size_t)tl * BB + p) * HH + tid];
    __syncthreads();
    if (tid < LAB) {
        float a = out_b[tid];
        for (int h = 0; h < HH; h++) a += s_rnn[h] * out_w[h * LAB + tid];
        out[g_perm[p] * LAB + tid] = a;
    }
}

// ---------------- launch ----------------
extern "C" void kernel_launch(void* const* d_in, const int* in_sizes, int n_in,
                              void* d_out, int out_size) {
    const float* X         = (const float*)d_in[0];
    const int*   vlen      = (const int*)  d_in[1];
    const float* kw        = (const float*)d_in[2];
    const float* kb        = (const float*)d_in[3];
    const float* rw        = (const float*)d_in[4];
    const float* rb        = (const float*)d_in[5];
    const float* scale_w   = (const float*)d_in[6];
    const float* scale_b   = (const float*)d_in[7];
    const float* rescale_w = (const float*)d_in[8];
    const float* rescale_b = (const float*)d_in[9];
    const float* conv_w    = (const float*)d_in[10];
    const float* conv_b    = (const float*)d_in[11];
    const float* out_w     = (const float*)d_in[12];
    const float* out_b     = (const float*)d_in[13];
    float* out = (float*)d_out;

    k_setup<<<1, 1>>>(vlen);
    k_zero<<<(BB * HH + 255) / 256, 256>>>();
    k_convT<<<(HH * HH * KW + 255) / 256, 256>>>(conv_w);
    k_prep<<<NPAD, 384>>>(kw, kb, rw, rb);

    k_gemm_pre_fp16<<<dim3(13, 1024), 256>>>(X);

    for (int t = 0; t < TT; t++) {
        k_step<<<dim3(24, 16), 256>>>(t);
    }

    k_fin1<<<BB, 256>>>(scale_w, scale_b, rescale_w, rescale_b);
    k_fin2<<<dim3(HH / 64, BB / 64), 256>>>();
    k_fin3<<<BB, HH>>>(conv_b, out_w, out_b, out);
}

// round 16
// speedup vs baseline: 1.5127x; 1.5127x over previous
#include <cuda_runtime.h>
#include <cuda_fp16.h>

#define BB 512
#define TT 128
#define FF 256
#define HH 384
#define LL 3
#define KW 10
#define LAB 25
#define GATES 1542
#define HID 64
#define CONVK (HH * KW)   // 3840
#define NPAD 1664         // 13*128
// permuted gate layout: col 4e+q (q: 0=f,1=i,2=o,3=c) for e in [0,384); cols 1536..1541 = fm/im raw

// ---------------- device scratch ----------------
__device__ __align__(16) int   g_perm[BB];
__device__ __align__(16) int   g_vlen[BB];
__device__ __align__(16) int   g_nact[TT];
__device__ float g_pre[(size_t)TT * BB * NPAD];               // 436 MB
__device__ __align__(16) float g_hbuf[2][BB * HH];            // ping-pong h state
__device__ __align__(16) float g_c[BB * HH];
__device__ __align__(16) float g_hist[(size_t)TT * BB * HH];  // 100 MB
__device__ __align__(16) float g_dish[TT * BB];
__device__ __align__(16) float g_convT[CONVK * HH];
__device__ __align__(16) float g_lh[BB * CONVK];
__device__ __align__(16) float g_theme[BB * HH];
__device__ __align__(16) float g_conv[BB * HH];
// fp16 split weights, transposed to [n][k], columns PERMUTED per layout above
__device__ __align__(16) __half g_BkwH[2][NPAD * FF];         // hi, lo
__device__ __align__(16) __half g_BrwH[2][NPAD * HH];
__device__ __align__(16) float g_bias0[NPAD];
__device__ __align__(16) float g_biasT[NPAD];

__device__ __forceinline__ float sigm(float x) { return 1.f / (1.f + expf(-x)); }

__device__ __forceinline__ void split2(float x, float y, unsigned& hi, unsigned& lo) {
    __half hx = __float2half_rn(x), hy = __float2half_rn(y);
    __half lx = __float2half_rn(x - __half2float(hx));
    __half ly = __float2half_rn(y - __half2float(hy));
    hi = ((unsigned)__half_as_ushort(hy) << 16) | (unsigned)__half_as_ushort(hx);
    lo = ((unsigned)__half_as_ushort(ly) << 16) | (unsigned)__half_as_ushort(lx);
}

#define MMA_F16(cc, a, b0, b1)                                                  \
    asm volatile("mma.sync.aligned.m16n8k16.row.col.f32.f16.f16.f32 "           \
        "{%0,%1,%2,%3}, {%4,%5,%6,%7}, {%8,%9}, {%0,%1,%2,%3};"                 \
        : "+f"((cc)[0]), "+f"((cc)[1]), "+f"((cc)[2]), "+f"((cc)[3])            \
        : "r"((a)[0]), "r"((a)[1]), "r"((a)[2]), "r"((a)[3]),                   \
          "r"(b0), "r"(b1))

// ---------------- setup ----------------
__global__ void k_setup(const int* __restrict__ vlen) {
    int cnt[129];
    for (int v = 0; v <= 128; v++) cnt[v] = 0;
    for (int b = 0; b < BB; b++) cnt[vlen[b]]++;
    int cur[129];
    int off = 0;
    for (int v = 128; v >= 1; v--) { cur[v] = off; off += cnt[v]; }
    for (int b = 0; b < BB; b++) {
        int v = vlen[b];
        int p = cur[v]++;
        g_perm[p] = b;
        g_vlen[p] = v;
    }
    int suf = 0;
    for (int t = TT - 1; t >= 0; t--) { suf += cnt[t + 1]; g_nact[t] = suf; }
}

__global__ void k_zero() {
    int i = blockIdx.x * blockDim.x + threadIdx.x;
    if (i < BB * HH) {
        g_hbuf[0][i] = 0.f;
        g_hbuf[1][i] = 0.f;
        g_c[i] = 0.f;
    }
}

__global__ void k_convT(const float* __restrict__ cw) {
    int i = blockIdx.x * blockDim.x + threadIdx.x;
    if (i >= HH * HH * KW) return;
    int k  = i % KW;
    int hh = (i / KW) % HH;
    int o  = i / (KW * HH);
    g_convT[(hh * KW + k) * HH + o] = cw[i];
}

// ---------------- prep: permute + split + transpose weights ----------------
__global__ void k_prep(const float* __restrict__ kw, const float* __restrict__ kb,
                       const float* __restrict__ rw, const float* __restrict__ rb) {
    int n = blockIdx.x;
    int k = threadIdx.x;
    int src;
    bool v;
    if (n < 1536)      { src = 6 + (n & 3) * HH + (n >> 2); v = true; }
    else if (n < 1542) { src = n - 1536; v = true; }
    else               { src = 0; v = false; }
    if (k < FF) {
        float w = v ? kw[k * GATES + src] : 0.f;
        __half hi = __float2half_rn(w);
        g_BkwH[0][n * FF + k] = hi;
        g_BkwH[1][n * FF + k] = __float2half_rn(w - __half2float(hi));
    }
    if (k < HH) {
        float w = v ? rw[k * GATES + src] : 0.f;
        __half hi = __float2half_rn(w);
        g_BrwH[0][n * HH + k] = hi;
        g_BrwH[1][n * HH + k] = __float2half_rn(w - __half2float(hi));
    }
    if (k == 0) {
        float b0 = v ? (kb[src] + rb[src]) : 0.f;
        float bT = b0 + (v ? (kw[FF * GATES + src] + rw[HH * GATES + src]) : 0.f);
        g_bias0[n] = b0;
        g_biasT[n] = bT;
    }
}

// ---------------- fp16 pre-GEMM: 64(t) x 128(n) tiles, vlen skip (R11-proven) ----------------
__global__ __launch_bounds__(256) void k_gemm_pre_fp16(const float* __restrict__ X) {
    __shared__ __half SA[2][64 * 24];    // [hi/lo], row stride 24 fp16
    __shared__ __half SB[2][128 * 24];

    int p  = blockIdx.y >> 1;
    int t0 = (blockIdx.y & 1) * 64;
    if (t0 >= g_vlen[p]) return;
    int n0 = blockIdx.x * 128;
    int tid = threadIdx.x;
    int lane = tid & 31, wid = tid >> 5;
    int wm = wid >> 2, wn = wid & 3;
    int g = lane >> 2, tq = lane & 3;
    const float* A = X + (size_t)g_perm[p] * (TT * FF) + (size_t)t0 * FF;

    int am = tid >> 2, ak = (tid & 3) * 4;
    int bm = tid >> 1, bk = (tid & 1) * 8;

    float c[2][4][4] = {};

    float4 va;
    uint4 vbh, vbl;
    va  = *(const float4*)(A + am * FF + ak);
    vbh = *(const uint4*)(&g_BkwH[0][(n0 + bm) * FF + bk]);
    vbl = *(const uint4*)(&g_BkwH[1][(n0 + bm) * FF + bk]);

    const int nK = FF / 16;  // 16
    for (int kt = 0; kt < nK; kt++) {
        {
            unsigned h0, l0, h1, l1;
            split2(va.x, va.y, h0, l0);
            split2(va.z, va.w, h1, l1);
            *(uint2*)&SA[0][am * 24 + ak] = make_uint2(h0, h1);
            *(uint2*)&SA[1][am * 24 + ak] = make_uint2(l0, l1);
            *(uint4*)&SB[0][bm * 24 + bk] = vbh;
            *(uint4*)&SB[1][bm * 24 + bk] = vbl;
        }
        __syncthreads();
        if (kt + 1 < nK) {
            int k0 = (kt + 1) * 16;
            va  = *(const float4*)(A + am * FF + k0 + ak);
            vbh = *(const uint4*)(&g_BkwH[0][(n0 + bm) * FF + k0 + bk]);
            vbl = *(const uint4*)(&g_BkwH[1][(n0 + bm) * FF + k0 + bk]);
        }

        const unsigned* sah = (const unsigned*)SA[0];
        const unsigned* sal = (const unsigned*)SA[1];
        const unsigned* sbh = (const unsigned*)SB[0];
        const unsigned* sbl = (const unsigned*)SB[1];

        unsigned ah[2][4], al[2][4];
        #pragma unroll
        for (int mf = 0; mf < 2; mf++) {
            int r = wm * 32 + mf * 16 + g;
            ah[mf][0] = sah[r * 12 + tq];
            ah[mf][1] = sah[(r + 8) * 12 + tq];
            ah[mf][2] = sah[r * 12 + tq + 4];
            ah[mf][3] = sah[(r + 8) * 12 + tq + 4];
            al[mf][0] = sal[r * 12 + tq];
            al[mf][1] = sal[(r + 8) * 12 + tq];
            al[mf][2] = sal[r * 12 + tq + 4];
            al[mf][3] = sal[(r + 8) * 12 + tq + 4];
        }
        #pragma unroll
        for (int nf = 0; nf < 4; nf++) {
            int nn = wn * 32 + nf * 8 + g;
            unsigned bh0 = sbh[nn * 12 + tq], bh1 = sbh[nn * 12 + tq + 4];
            unsigned bl0 = sbl[nn * 12 + tq], bl1 = sbl[nn * 12 + tq + 4];
            #pragma unroll
            for (int mf = 0; mf < 2; mf++) {
                MMA_F16(c[mf][nf], ah[mf], bh0, bh1);
                MMA_F16(c[mf][nf], ah[mf], bl0, bl1);
                MMA_F16(c[mf][nf], al[mf], bh0, bh1);
            }
        }
        __syncthreads();
    }

    #pragma unroll
    for (int mf = 0; mf < 2; mf++) {
        int r0 = wm * 32 + mf * 16 + g;
        int r1 = r0 + 8;
        int ta = t0 + r0, tb = t0 + r1;
        #pragma unroll
        for (int nf = 0; nf < 4; nf++) {
            int col = n0 + wn * 32 + nf * 8 + 2 * tq;
            float b0a = (ta == 0) ? g_bias0[col] : g_biasT[col];
            float b0b = (ta == 0) ? g_bias0[col + 1] : g_biasT[col + 1];
            float2 v;
            v.x = c[mf][nf][0] + b0a;
            v.y = c[mf][nf][1] + b0b;
            *(float2*)&g_pre[((size_t)ta * BB + p) * NPAD + col] = v;
            v.x = c[mf][nf][2] + g_biasT[col];
            v.y = c[mf][nf][3] + g_biasT[col + 1];
            *(float2*)&g_pre[((size_t)tb * BB + p) * NPAD + col] = v;
        }
    }
}

// ---------------- fused step: K split across warps (wk), double-buffered ----------------
// grid (24, 16), 256 thr, 8 warps (wk, wm, wn). Each wk-half owns 12 of 24 k-tiles;
// partial accumulators reduced through smem at the end. Reads g_hbuf[t&1], writes
// g_hbuf[(t+1)&1] — no cross-block hazards.
__global__ __launch_bounds__(256) void k_step(int t) {
    __shared__ __half SA[2][2][2][32 * 24];   // [stage][khalf][hi/lo]
    __shared__ __half SB[2][2][2][72 * 24];
    __shared__ float SR[4][32][20];           // wk=1 partials: 16 c + 4 csp
    __shared__ float SX[32 * 76];
    __shared__ float sfm[32], sim[32];

    int na = g_nact[t];
    int m0 = blockIdx.y * 32;
    if (m0 >= na) return;
    int n0 = blockIdx.x * 64;
    int e0 = blockIdx.x * 16;
    int tid = threadIdx.x;
    int lane = tid & 31, wid = tid >> 5;
    int wk = wid >> 2;
    int wm = (wid >> 1) & 1, wn = wid & 1;
    int g = lane >> 2, tq = lane & 3;

    int t7 = tid & 127;
    int kh = tid >> 7;                       // loader's k-half
    int am = t7 >> 2, ak = (t7 & 3) * 4;
    int bm = t7 >> 1, bk = (t7 & 1) * 8;
    int kbase = kh * 192;                    // 12 k-tiles * 16
    const float* A = g_hbuf[t & 1] + m0 * HH;
    float* Hout = g_hbuf[(t + 1) & 1];

    float c[4][4] = {};
    float csp[4] = {};

    float4 va;
    uint4 vbh, vbl, vsh, vsl;

    // prologue: each 128-thread group loads k-tile 0 of its half into stage 0
    va  = *(const float4*)(A + am * HH + kbase + ak);
    vbh = *(const uint4*)(&g_BrwH[0][(n0 + bm) * HH + kbase + bk]);
    vbl = *(const uint4*)(&g_BrwH[1][(n0 + bm) * HH + kbase + bk]);
    if (t7 < 16) {
        vsh = *(const uint4*)(&g_BrwH[0][(1536 + bm) * HH + kbase + bk]);
        vsl = *(const uint4*)(&g_BrwH[1][(1536 + bm) * HH + kbase + bk]);
    }
    {
        unsigned h0, l0, h1, l1;
        split2(va.x, va.y, h0, l0);
        split2(va.z, va.w, h1, l1);
        *(uint2*)&SA[0][kh][0][am * 24 + ak] = make_uint2(h0, h1);
        *(uint2*)&SA[0][kh][1][am * 24 + ak] = make_uint2(l0, l1);
        *(uint4*)&SB[0][kh][0][bm * 24 + bk] = vbh;
        *(uint4*)&SB[0][kh][1][bm * 24 + bk] = vbl;
        if (t7 < 16) {
            *(uint4*)&SB[0][kh][0][(64 + bm) * 24 + bk] = vsh;
            *(uint4*)&SB[0][kh][1][(64 + bm) * 24 + bk] = vsl;
        }
    }
    __syncthreads();

    const int nIT = 12;
    for (int it = 0; it < nIT; it++) {
        int cur = it & 1;
        bool more = (it + 1 < nIT);
        if (more) {
            int k0 = kbase + (it + 1) * 16;
            va  = *(const float4*)(A + am * HH + k0 + ak);
            vbh = *(const uint4*)(&g_BrwH[0][(n0 + bm) * HH + k0 + bk]);
            vbl = *(const uint4*)(&g_BrwH[1][(n0 + bm) * HH + k0 + bk]);
            if (t7 < 16) {
                vsh = *(const uint4*)(&g_BrwH[0][(1536 + bm) * HH + k0 + bk]);
                vsl = *(const uint4*)(&g_BrwH[1][(1536 + bm) * HH + k0 + bk]);
            }
        }

        const unsigned* sah = (const unsigned*)SA[cur][wk][0];
        const unsigned* sal = (const unsigned*)SA[cur][wk][1];
        const unsigned* sbh = (const unsigned*)SB[cur][wk][0];
        const unsigned* sbl = (const unsigned*)SB[cur][wk][1];

        unsigned ah[4], al[4];
        int r = wm * 16 + g;
        ah[0] = sah[r * 12 + tq];
        ah[1] = sah[(r + 8) * 12 + tq];
        ah[2] = sah[r * 12 + tq + 4];
        ah[3] = sah[(r + 8) * 12 + tq + 4];
        al[0] = sal[r * 12 + tq];
        al[1] = sal[(r + 8) * 12 + tq];
        al[2] = sal[r * 12 + tq + 4];
        al[3] = sal[(r + 8) * 12 + tq + 4];

        #pragma unroll
        for (int nf = 0; nf < 4; nf++) {
            int nn = wn * 32 + nf * 8 + g;
            unsigned bh0 = sbh[nn * 12 + tq], bh1 = sbh[nn * 12 + tq + 4];
            unsigned bl0 = sbl[nn * 12 + tq], bl1 = sbl[nn * 12 + tq + 4];
            MMA_F16(c[nf], ah, bh0, bh1);
            MMA_F16(c[nf], ah, bl0, bl1);
            MMA_F16(c[nf], al, bh0, bh1);
        }
        if (wn == 0) {
            int nn = 64 + g;
            unsigned bh0 = sbh[nn * 12 + tq], bh1 = sbh[nn * 12 + tq + 4];
            unsigned bl0 = sbl[nn * 12 + tq], bl1 = sbl[nn * 12 + tq + 4];
            MMA_F16(csp, ah, bh0, bh1);
            MMA_F16(csp, ah, bl0, bl1);
            MMA_F16(csp, al, bh0, bh1);
        }

        if (more) {
            int nxt = cur ^ 1;
            unsigned h0, l0, h1, l1;
            split2(va.x, va.y, h0, l0);
            split2(va.z, va.w, h1, l1);
            *(uint2*)&SA[nxt][kh][0][am * 24 + ak] = make_uint2(h0, h1);
            *(uint2*)&SA[nxt][kh][1][am * 24 + ak] = make_uint2(l0, l1);
            *(uint4*)&SB[nxt][kh][0][bm * 24 + bk] = vbh;
            *(uint4*)&SB[nxt][kh][1][bm * 24 + bk] = vbl;
            if (t7 < 16) {
                *(uint4*)&SB[nxt][kh][0][(64 + bm) * 24 + bk] = vsh;
                *(uint4*)&SB[nxt][kh][1][(64 + bm) * 24 + bk] = vsl;
            }
        }
        __syncthreads();
    }

    // cross-wk reduction: wk=1 dumps partials, wk=0 accumulates
    if (wk == 1) {
        int w = wm * 2 + wn;
        #pragma unroll
        for (int nf = 0; nf < 4; nf++)
            #pragma unroll
            for (int q = 0; q < 4; q++)
                SR[w][lane][nf * 4 + q] = c[nf][q];
        if (wn == 0) {
            #pragma unroll
            for (int q = 0; q < 4; q++) SR[w][lane][16 + q] = csp[q];
        }
    }
    __syncthreads();

    if (wk == 0) {
        int w = wm * 2 + wn;
        #pragma unroll
        for (int nf = 0; nf < 4; nf++)
            #pragma unroll
            for (int q = 0; q < 4; q++)
                c[nf][q] += SR[w][lane][nf * 4 + q];
        if (wn == 0) {
            #pragma unroll
            for (int q = 0; q < 4; q++) csp[q] += SR[w][lane][16 + q];
        }

        // write xo tile (acc + pre) to smem
        const float* pre = g_pre + (size_t)t * BB * NPAD;
        int r0 = wm * 16 + g;
        int r1 = r0 + 8;
        #pragma unroll
        for (int nf = 0; nf < 4; nf++) {
            int cc = wn * 32 + nf * 8 + 2 * tq;
            const float* p0 = &pre[(size_t)(m0 + r0) * NPAD + n0 + cc];
            const float* p1 = &pre[(size_t)(m0 + r1) * NPAD + n0 + cc];
            SX[r0 * 76 + cc]     = c[nf][0] + p0[0];
            SX[r0 * 76 + cc + 1] = c[nf][1] + p0[1];
            SX[r1 * 76 + cc]     = c[nf][2] + p1[0];
            SX[r1 * 76 + cc + 1] = c[nf][3] + p1[1];
        }
        if (wn == 0) {
            int cc = 64 + 2 * tq;
            const float* p0 = &pre[(size_t)(m0 + r0) * NPAD + 1536 + 2 * tq];
            const float* p1 = &pre[(size_t)(m0 + r1) * NPAD + 1536 + 2 * tq];
            SX[r0 * 76 + cc]     = csp[0] + p0[0];
            SX[r0 * 76 + cc + 1] = csp[1] + p0[1];
            SX[r1 * 76 + cc]     = csp[2] + p1[0];
            SX[r1 * 76 + cc + 1] = csp[3] + p1[1];
        }
    }
    __syncthreads();

    // per-row cumax softmax from special cols (threads 0..31)
    if (tid < 32) {
        int row = tid;
        float a0 = SX[row * 76 + 64], a1 = SX[row * 76 + 65], a2 = SX[row * 76 + 66];
        float m = fmaxf(a0, fmaxf(a1, a2));
        float e0v = expf(a0 - m), e1v = expf(a1 - m), e2v = expf(a2 - m);
        float inv = 1.f / (e0v + e1v + e2v);
        float fm0 = e0v * inv, fm1 = (e0v + e1v) * inv, fm2 = (e0v + e1v + e2v) * inv;
        float b0 = SX[row * 76 + 67], b1 = SX[row * 76 + 68], b2 = SX[row * 76 + 69];
        float mb = fmaxf(b0, fmaxf(b1, b2));
        float f0 = expf(b0 - mb), f1 = expf(b1 - mb), f2 = expf(b2 - mb);
        float invb = 1.f / (f0 + f1 + f2);
        float im0 = (f0 + f1 + f2) * invb, im1 = (f1 + f2) * invb, im2 = f2 * invb;
        int l = e0 >> 7;
        sfm[row] = (l == 0) ? fm0 : ((l == 1) ? fm1 : fm2);
        sim[row] = (l == 0) ? im0 : ((l == 1) ? im1 : im2);
        if (blockIdx.x == 0)
            g_dish[t * BB + m0 + row] = 1.f - (fm0 + fm1 + fm2) * (1.f / 3.f);
    }
    __syncthreads();

    // in-block pointwise for 32 rows x 16 elements (256 threads, 2 iters)
    #pragma unroll
    for (int i = 0; i < 2; i++) {
        int idx = tid + i * 256;
        int row = idx >> 4;
        int le = idx & 15;
        int ge = e0 + le;
        int p = m0 + row;
        const float* x4 = &SX[row * 76 + le * 4];
        float fg = sigm(x4[0]);
        float ig = sigm(x4[1]);
        float og = sigm(x4[2]);
        float ci = tanhf(x4[3]);
        float fm = sfm[row], im = sim[row], ov = fm * im;
        float cl = g_c[p * HH + ge];
        float cn = ov * (fg * cl + ig * ci) + (fm - ov) * cl + (im - ov) * ci;
        float hn = og * tanhf(cn);
        g_c[p * HH + ge] = cn;
        Hout[p * HH + ge] = hn;
        g_hist[((size_t)t * BB + p) * HH + ge] = hn;
    }
}

// ---------------- batched epilogue ----------------
__global__ void k_fin1(const float* __restrict__ scale_w, const float* __restrict__ scale_b,
                       const float* __restrict__ rescale_w, const float* __restrict__ rescale_b) {
    int p = blockIdx.x;
    int tl = g_vlen[p] - 1;
    int tid = threadIdx.x;
    __shared__ float s_ldis[KW];
    __shared__ float s_th[HH];
    __shared__ float s_r1[HID];

    if (tid == 0) {
        float buf[KW];
        float cs = 0.f;
        #pragma unroll
        for (int k = 0; k < KW; k++) {
            int s = tl - (KW - 1) + k;
            cs += (s >= 0) ? g_dish[s * BB + p] : 0.f;
            buf[k] = cs;
        }
        float m = buf[0];
        #pragma unroll
        for (int k = 1; k < KW; k++) m = fmaxf(m, buf[k]);
        float sum = 0.f;
        #pragma unroll
        for (int k = 0; k < KW; k++) { buf[k] = expf(buf[k] - m); sum += buf[k]; }
        float invs = 1.f / sum;
        #pragma unroll
        for (int k = 0; k < KW; k++) s_ldis[k] = buf[k] * invs;
    }
    __syncthreads();

    for (int e = tid; e < HH; e += 256) {
        float tp = 0.f;
        #pragma unroll
        for (int k = 0; k < KW; k++) {
            int s = tl - (KW - 1) + k;
            float hv = (s >= 0) ? g_hist[((size_t)s * BB + p) * HH + e] : 0.f;
            float lv = hv * s_ldis[k];
            g_lh[(size_t)p * CONVK + e * KW + k] = lv;
            tp += lv;
        }
        s_th[e] = tp * (1.f / KW);
    }
    __syncthreads();

    if (tid < HID) {
        float a = scale_b[tid];
        for (int h = 0; h < HH; h++) a += s_th[h] * scale_w[h * HID + tid];
        s_r1[tid] = fmaxf(a, 0.f);
    }
    __syncthreads();

    for (int e = tid; e < HH; e += 256) {
        float th2 = rescale_b[e];
        #pragma unroll 8
        for (int j = 0; j < HID; j++) th2 += s_r1[j] * rescale_w[j * HH + e];
        g_theme[p * HH + e] = sigm(th2);
    }
}

// fin2: conv GEMM  g_conv[512,384] = g_lh[512,3840] @ g_convT[3840,384]
__global__ void k_fin2() {
    __shared__ float As[16][68];
    __shared__ float Bs[16][68];
    int m0 = blockIdx.y * 64;
    int nb = blockIdx.x * 64;
    int tid  = threadIdx.x;
    int ty   = tid >> 4, tx = tid & 15;
    int arow = tid >> 2, akk = (tid & 3) << 2;
    int bk   = tid >> 4, bn  = (tid & 15) << 2;
    float acc[4][4] = {};
    const float* A = g_lh + (size_t)m0 * CONVK;

    float4 a_nxt = *(const float4*)(A + (size_t)arow * CONVK + akk);
    float4 b_nxt = *(const float4*)(g_convT + bk * HH + nb + bn);

    for (int k0 = 0; k0 < CONVK; k0 += 16) {
        As[akk + 0][arow] = a_nxt.x; As[akk + 1][arow] = a_nxt.y;
        As[akk + 2][arow] = a_nxt.z; As[akk + 3][arow] = a_nxt.w;
        *(float4*)&Bs[bk][bn] = b_nxt;
        __syncthreads();
        if (k0 + 16 < CONVK) {
            a_nxt = *(const float4*)(A + (size_t)arow * CONVK + k0 + 16 + akk);
            b_nxt = *(const float4*)(g_convT + (k0 + 16 + bk) * HH + nb + bn);
        }
        #pragma unroll
        for (int k = 0; k < 16; k++) {
            float4 a = *(const float4*)&As[k][ty * 4];
            float4 b = *(const float4*)&Bs[k][tx * 4];
            float avr[4] = {a.x, a.y, a.z, a.w};
            float bvr[4] = {b.x, b.y, b.z, b.w};
            #pragma unroll
            for (int i = 0; i < 4; i++)
                #pragma unroll
                for (int j = 0; j < 4; j++) acc[i][j] += avr[i] * bvr[j];
        }
        __syncthreads();
    }
    #pragma unroll
    for (int i = 0; i < 4; i++)
        #pragma unroll
        for (int j = 0; j < 4; j++)
            g_conv[(m0 + ty * 4 + i) * HH + nb + tx * 4 + j] = acc[i][j];
}

__global__ void k_fin3(const float* __restrict__ conv_b, const float* __restrict__ out_w,
                       const float* __restrict__ out_b, float* __restrict__ out) {
    int p = blockIdx.x;
    int tid = threadIdx.x;
    int tl = g_vlen[p] - 1;
    __shared__ float s_rnn[HH];
    s_rnn[tid] = g_theme[p * HH + tid] * (g_conv[p * HH + tid] + conv_b[tid])
               + g_hist[((size_t)tl * BB + p) * HH + tid];
    __syncthreads();
    if (tid < LAB) {
        float a = out_b[tid];
        for (int h = 0; h < HH; h++) a += s_rnn[h] * out_w[h * LAB + tid];
        out[g_perm[p] * LAB + tid] = a;
    }
}

// ---------------- launch ----------------
extern "C" void kernel_launch(void* const* d_in, const int* in_sizes, int n_in,
                              void* d_out, int out_size) {
    const float* X         = (const float*)d_in[0];
    const int*   vlen      = (const int*)  d_in[1];
    const float* kw        = (const float*)d_in[2];
    const float* kb        = (const float*)d_in[3];
    const float* rw        = (const float*)d_in[4];
    const float* rb        = (const float*)d_in[5];
    const float* scale_w   = (const float*)d_in[6];
    const float* scale_b   = (const float*)d_in[7];
    const float* rescale_w = (const float*)d_in[8];
    const float* rescale_b = (const float*)d_in[9];
    const float* conv_w    = (const float*)d_in[10];
    const float* conv_b    = (const float*)d_in[11];
    const float* out_w     = (const float*)d_in[12];
    const float* out_b     = (const float*)d_in[13];
    float* out = (float*)d_out;

    k_setup<<<1, 1>>>(vlen);
    k_zero<<<(BB * HH + 255) / 256, 256>>>();
    k_convT<<<(HH * HH * KW + 255) / 256, 256>>>(conv_w);
    k_prep<<<NPAD, 384>>>(kw, kb, rw, rb);

    k_gemm_pre_fp16<<<dim3(13, 1024), 256>>>(X);

    for (int t = 0; t < TT; t++) {
        k_step<<<dim3(24, 16), 256>>>(t);
    }

    k_fin1<<<BB, 256>>>(scale_w, scale_b, rescale_w, rescale_b);
    k_fin2<<<dim3(HH / 64, BB / 64), 256>>>();
    k_fin3<<<BB, HH>>>(conv_b, out_w, out_b, out);
}

// round 17
// speedup vs baseline: 1.5892x; 1.0506x over previous
#include <cuda_runtime.h>
#include <cuda_fp16.h>

#define BB 512
#define TT 128
#define FF 256
#define HH 384
#define LL 3
#define KW 10
#define LAB 25
#define GATES 1542
#define HID 64
#define CONVK (HH * KW)   // 3840
#define NPAD 1664         // 13*128
// permuted gate layout: col 4e+q (q: 0=f,1=i,2=o,3=c) for e in [0,384); cols 1536..1541 = fm/im raw

// ---------------- device scratch ----------------
__device__ __align__(16) int   g_perm[BB];
__device__ __align__(16) int   g_vlen[BB];
__device__ __align__(16) int   g_nact[TT];
__device__ __align__(16) int   g_rowoff[BB + 1];
__device__ __align__(16) int   g_rowidx[BB * TT];             // packed t<<16 | p, prefix rows only
__device__ int   g_nrows;
__device__ float g_pre[(size_t)TT * BB * NPAD];               // 436 MB
__device__ __align__(16) float g_hbuf[2][BB * HH];            // ping-pong h state
__device__ __align__(16) float g_c[BB * HH];
__device__ __align__(16) float g_hist[(size_t)TT * BB * HH];  // 100 MB
__device__ __align__(16) float g_dish[TT * BB];
__device__ __align__(16) float g_convT[CONVK * HH];
__device__ __align__(16) float g_lh[BB * CONVK];
__device__ __align__(16) float g_theme[BB * HH];
__device__ __align__(16) float g_conv[BB * HH];
// fp16 split weights, transposed to [n][k], columns PERMUTED per layout above
__device__ __align__(16) __half g_BkwH[2][NPAD * FF];         // hi, lo
__device__ __align__(16) __half g_BrwH[2][NPAD * HH];
__device__ __align__(16) float g_bias0[NPAD];
__device__ __align__(16) float g_biasT[NPAD];

__device__ __forceinline__ float sigm(float x) { return 1.f / (1.f + expf(-x)); }

__device__ __forceinline__ void split2(float x, float y, unsigned& hi, unsigned& lo) {
    __half hx = __float2half_rn(x), hy = __float2half_rn(y);
    __half lx = __float2half_rn(x - __half2float(hx));
    __half ly = __float2half_rn(y - __half2float(hy));
    hi = ((unsigned)__half_as_ushort(hy) << 16) | (unsigned)__half_as_ushort(hx);
    lo = ((unsigned)__half_as_ushort(ly) << 16) | (unsigned)__half_as_ushort(lx);
}

#define MMA_F16(cc, a, b0, b1)                                                  \
    asm volatile("mma.sync.aligned.m16n8k16.row.col.f32.f16.f16.f32 "           \
        "{%0,%1,%2,%3}, {%4,%5,%6,%7}, {%8,%9}, {%0,%1,%2,%3};"                 \
        : "+f"((cc)[0]), "+f"((cc)[1]), "+f"((cc)[2]), "+f"((cc)[3])            \
        : "r"((a)[0]), "r"((a)[1]), "r"((a)[2]), "r"((a)[3]),                   \
          "r"(b0), "r"(b1))

// ---------------- setup ----------------
__global__ void k_setup(const int* __restrict__ vlen) {
    int cnt[129];
    for (int v = 0; v <= 128; v++) cnt[v] = 0;
    for (int b = 0; b < BB; b++) cnt[vlen[b]]++;
    int cur[129];
    int off = 0;
    for (int v = 128; v >= 1; v--) { cur[v] = off; off += cnt[v]; }
    for (int b = 0; b < BB; b++) {
        int v = vlen[b];
        int p = cur[v]++;
        g_perm[p] = b;
        g_vlen[p] = v;
    }
    int suf = 0;
    for (int t = TT - 1; t >= 0; t--) { suf += cnt[t + 1]; g_nact[t] = suf; }
    // prefix offsets for compacted (t,p) row list (p-major)
    int acc = 0;
    for (int p = 0; p < BB; p++) { g_rowoff[p] = acc; acc += g_vlen[p]; }
    g_rowoff[BB] = acc;
    g_nrows = acc;
}

// fill compacted row list: row r in [rowoff[p], rowoff[p]+vlen[p]) -> (t = r-rowoff[p], p)
__global__ void k_rows() {
    int p = blockIdx.x;
    int off = g_rowoff[p];
    int v = g_vlen[p];
    for (int t = threadIdx.x; t < v; t += blockDim.x)
        g_rowidx[off + t] = (t << 16) | p;
}

__global__ void k_zero() {
    int i = blockIdx.x * blockDim.x + threadIdx.x;
    if (i < BB * HH) {
        g_hbuf[0][i] = 0.f;
        g_hbuf[1][i] = 0.f;
        g_c[i] = 0.f;
    }
}

__global__ void k_convT(const float* __restrict__ cw) {
    int i = blockIdx.x * blockDim.x + threadIdx.x;
    if (i >= HH * HH * KW) return;
    int k  = i % KW;
    int hh = (i / KW) % HH;
    int o  = i / (KW * HH);
    g_convT[(hh * KW + k) * HH + o] = cw[i];
}

// ---------------- prep: permute + split + transpose weights ----------------
__global__ void k_prep(const float* __restrict__ kw, const float* __restrict__ kb,
                       const float* __restrict__ rw, const float* __restrict__ rb) {
    int n = blockIdx.x;
    int k = threadIdx.x;
    int src;
    bool v;
    if (n < 1536)      { src = 6 + (n & 3) * HH + (n >> 2); v = true; }
    else if (n < 1542) { src = n - 1536; v = true; }
    else               { src = 0; v = false; }
    if (k < FF) {
        float w = v ? kw[k * GATES + src] : 0.f;
        __half hi = __float2half_rn(w);
        g_BkwH[0][n * FF + k] = hi;
        g_BkwH[1][n * FF + k] = __float2half_rn(w - __half2float(hi));
    }
    if (k < HH) {
        float w = v ? rw[k * GATES + src] : 0.f;
        __half hi = __float2half_rn(w);
        g_BrwH[0][n * HH + k] = hi;
        g_BrwH[1][n * HH + k] = __float2half_rn(w - __half2float(hi));
    }
    if (k == 0) {
        float b0 = v ? (kb[src] + rb[src]) : 0.f;
        float bT = b0 + (v ? (kw[FF * GATES + src] + rw[HH * GATES + src]) : 0.f);
        g_bias0[n] = b0;
        g_biasT[n] = bT;
    }
}

// ---------------- fp16 pre-GEMM over COMPACTED rows: 64(row) x 128(n) tiles ----------------
// grid (13, 1024): m0 = by*64 over g_nrows compacted (t,p) rows; skip if beyond.
__global__ __launch_bounds__(256) void k_gemm_pre_fp16(const float* __restrict__ X) {
    __shared__ __half SA[2][64 * 24];    // [hi/lo], row stride 24 fp16
    __shared__ __half SB[2][128 * 24];

    int nrows = g_nrows;
    int m0 = blockIdx.y * 64;
    if (m0 >= nrows) return;
    int n0 = blockIdx.x * 128;
    int tid = threadIdx.x;
    int lane = tid & 31, wid = tid >> 5;
    int wm = wid >> 2, wn = wid & 3;
    int g = lane >> 2, tq = lane & 3;

    int am = tid >> 2, ak = (tid & 3) * 4;   // A: 64 rows x 16 fp32, float4 each
    int bm = tid >> 1, bk = (tid & 1) * 8;   // B: 128 rows x 16 fp16, uint4 per layer

    // resolve this thread's A row (clamped; OOB rows masked at epilogue)
    int ar = m0 + am;
    int ridx = g_rowidx[(ar < nrows) ? ar : (nrows - 1)];
    const float* A = X + (size_t)g_perm[ridx & 0xFFFF] * (TT * FF)
                       + (size_t)(ridx >> 16) * FF;

    float c[2][4][4] = {};

    float4 va;
    uint4 vbh, vbl;
    va  = *(const float4*)(A + ak);
    vbh = *(const uint4*)(&g_BkwH[0][(n0 + bm) * FF + bk]);
    vbl = *(const uint4*)(&g_BkwH[1][(n0 + bm) * FF + bk]);

    const int nK = FF / 16;  // 16
    for (int kt = 0; kt < nK; kt++) {
        {
            unsigned h0, l0, h1, l1;
            split2(va.x, va.y, h0, l0);
            split2(va.z, va.w, h1, l1);
            *(uint2*)&SA[0][am * 24 + ak] = make_uint2(h0, h1);
            *(uint2*)&SA[1][am * 24 + ak] = make_uint2(l0, l1);
            *(uint4*)&SB[0][bm * 24 + bk] = vbh;
            *(uint4*)&SB[1][bm * 24 + bk] = vbl;
        }
        __syncthreads();
        if (kt + 1 < nK) {
            int k0 = (kt + 1) * 16;
            va  = *(const float4*)(A + k0 + ak);
            vbh = *(const uint4*)(&g_BkwH[0][(n0 + bm) * FF + k0 + bk]);
            vbl = *(const uint4*)(&g_BkwH[1][(n0 + bm) * FF + k0 + bk]);
        }

        const unsigned* sah = (const unsigned*)SA[0];
        const unsigned* sal = (const unsigned*)SA[1];
        const unsigned* sbh = (const unsigned*)SB[0];
        const unsigned* sbl = (const unsigned*)SB[1];

        unsigned ah[2][4], al[2][4];
        #pragma unroll
        for (int mf = 0; mf < 2; mf++) {
            int r = wm * 32 + mf * 16 + g;
            ah[mf][0] = sah[r * 12 + tq];
            ah[mf][1] = sah[(r + 8) * 12 + tq];
            ah[mf][2] = sah[r * 12 + tq + 4];
            ah[mf][3] = sah[(r + 8) * 12 + tq + 4];
            al[mf][0] = sal[r * 12 + tq];
            al[mf][1] = sal[(r + 8) * 12 + tq];
            al[mf][2] = sal[r * 12 + tq + 4];
            al[mf][3] = sal[(r + 8) * 12 + tq + 4];
        }
        #pragma unroll
        for (int nf = 0; nf < 4; nf++) {
            int nn = wn * 32 + nf * 8 + g;
            unsigned bh0 = sbh[nn * 12 + tq], bh1 = sbh[nn * 12 + tq + 4];
            unsigned bl0 = sbl[nn * 12 + tq], bl1 = sbl[nn * 12 + tq + 4];
            #pragma unroll
            for (int mf = 0; mf < 2; mf++) {
                MMA_F16(c[mf][nf], ah[mf], bh0, bh1);
                MMA_F16(c[mf][nf], ah[mf], bl0, bl1);
                MMA_F16(c[mf][nf], al[mf], bh0, bh1);
            }
        }
        __syncthreads();
    }

    #pragma unroll
    for (int mf = 0; mf < 2; mf++) {
        int r0 = m0 + wm * 32 + mf * 16 + g;
        int r1 = r0 + 8;
        #pragma unroll
        for (int rr = 0; rr < 2; rr++) {
            int r = rr ? r1 : r0;
            if (r >= nrows) continue;
            int idx = g_rowidx[r];
            int ta = idx >> 16, pa = idx & 0xFFFF;
            float* dst = &g_pre[((size_t)ta * BB + pa) * NPAD];
            const float* bias = (ta == 0) ? g_bias0 : g_biasT;
            #pragma unroll
            for (int nf = 0; nf < 4; nf++) {
                int col = n0 + wn * 32 + nf * 8 + 2 * tq;
                float2 v;
                v.x = c[mf][nf][rr * 2 + 0] + bias[col];
                v.y = c[mf][nf][rr * 2 + 1] + bias[col + 1];
                *(float2*)&dst[col] = v;
            }
        }
    }
}

// ---------------- fused step: K split across warps (wk), double-buffered ----------------
// grid (24, 16), 256 thr, 8 warps (wk, wm, wn). Each wk-half owns 12 of 24 k-tiles;
// partial accumulators reduced through smem at the end. Reads g_hbuf[t&1], writes
// g_hbuf[(t+1)&1] — no cross-block hazards.
__global__ __launch_bounds__(256) void k_step(int t) {
    __shared__ __half SA[2][2][2][32 * 24];   // [stage][khalf][hi/lo]
    __shared__ __half SB[2][2][2][72 * 24];
    __shared__ float SR[4][32][20];           // wk=1 partials: 16 c + 4 csp
    __shared__ float SX[32 * 76];
    __shared__ float sfm[32], sim[32];

    int na = g_nact[t];
    int m0 = blockIdx.y * 32;
    if (m0 >= na) return;
    int n0 = blockIdx.x * 64;
    int e0 = blockIdx.x * 16;
    int tid = threadIdx.x;
    int lane = tid & 31, wid = tid >> 5;
    int wk = wid >> 2;
    int wm = (wid >> 1) & 1, wn = wid & 1;
    int g = lane >> 2, tq = lane & 3;

    int t7 = tid & 127;
    int kh = tid >> 7;                       // loader's k-half
    int am = t7 >> 2, ak = (t7 & 3) * 4;
    int bm = t7 >> 1, bk = (t7 & 1) * 8;
    int kbase = kh * 192;                    // 12 k-tiles * 16
    const float* A = g_hbuf[t & 1] + m0 * HH;
    float* Hout = g_hbuf[(t + 1) & 1];

    float c[4][4] = {};
    float csp[4] = {};

    float4 va;
    uint4 vbh, vbl, vsh, vsl;

    // prologue: each 128-thread group loads k-tile 0 of its half into stage 0
    va  = *(const float4*)(A + am * HH + kbase + ak);
    vbh = *(const uint4*)(&g_BrwH[0][(n0 + bm) * HH + kbase + bk]);
    vbl = *(const uint4*)(&g_BrwH[1][(n0 + bm) * HH + kbase + bk]);
    if (t7 < 16) {
        vsh = *(const uint4*)(&g_BrwH[0][(1536 + bm) * HH + kbase + bk]);
        vsl = *(const uint4*)(&g_BrwH[1][(1536 + bm) * HH + kbase + bk]);
    }
    {
        unsigned h0, l0, h1, l1;
        split2(va.x, va.y, h0, l0);
        split2(va.z, va.w, h1, l1);
        *(uint2*)&SA[0][kh][0][am * 24 + ak] = make_uint2(h0, h1);
        *(uint2*)&SA[0][kh][1][am * 24 + ak] = make_uint2(l0, l1);
        *(uint4*)&SB[0][kh][0][bm * 24 + bk] = vbh;
        *(uint4*)&SB[0][kh][1][bm * 24 + bk] = vbl;
        if (t7 < 16) {
            *(uint4*)&SB[0][kh][0][(64 + bm) * 24 + bk] = vsh;
            *(uint4*)&SB[0][kh][1][(64 + bm) * 24 + bk] = vsl;
        }
    }
    __syncthreads();

    const int nIT = 12;
    for (int it = 0; it < nIT; it++) {
        int cur = it & 1;
        bool more = (it + 1 < nIT);
        if (more) {
            int k0 = kbase + (it + 1) * 16;
            va  = *(const float4*)(A + am * HH + k0 + ak);
            vbh = *(const uint4*)(&g_BrwH[0][(n0 + bm) * HH + k0 + bk]);
            vbl = *(const uint4*)(&g_BrwH[1][(n0 + bm) * HH + k0 + bk]);
            if (t7 < 16) {
                vsh = *(const uint4*)(&g_BrwH[0][(1536 + bm) * HH + k0 + bk]);
                vsl = *(const uint4*)(&g_BrwH[1][(1536 + bm) * HH + k0 + bk]);
            }
        }

        const unsigned* sah = (const unsigned*)SA[cur][wk][0];
        const unsigned* sal = (const unsigned*)SA[cur][wk][1];
        const unsigned* sbh = (const unsigned*)SB[cur][wk][0];
        const unsigned* sbl = (const unsigned*)SB[cur][wk][1];

        unsigned ah[4], al[4];
        int r = wm * 16 + g;
        ah[0] = sah[r * 12 + tq];
        ah[1] = sah[(r + 8) * 12 + tq];
        ah[2] = sah[r * 12 + tq + 4];
        ah[3] = sah[(r + 8) * 12 + tq + 4];
        al[0] = sal[r * 12 + tq];
        al[1] = sal[(r + 8) * 12 + tq];
        al[2] = sal[r * 12 + tq + 4];
        al[3] = sal[(r + 8) * 12 + tq + 4];

        #pragma unroll
        for (int nf = 0; nf < 4; nf++) {
            int nn = wn * 32 + nf * 8 + g;
            unsigned bh0 = sbh[nn * 12 + tq], bh1 = sbh[nn * 12 + tq + 4];
            unsigned bl0 = sbl[nn * 12 + tq], bl1 = sbl[nn * 12 + tq + 4];
            MMA_F16(c[nf], ah, bh0, bh1);
            MMA_F16(c[nf], ah, bl0, bl1);
            MMA_F16(c[nf], al, bh0, bh1);
        }
        if (wn == 0) {
            int nn = 64 + g;
            unsigned bh0 = sbh[nn * 12 + tq], bh1 = sbh[nn * 12 + tq + 4];
            unsigned bl0 = sbl[nn * 12 + tq], bl1 = sbl[nn * 12 + tq + 4];
            MMA_F16(csp, ah, bh0, bh1);
            MMA_F16(csp, ah, bl0, bl1);
            MMA_F16(csp, al, bh0, bh1);
        }

        if (more) {
            int nxt = cur ^ 1;
            unsigned h0, l0, h1, l1;
            split2(va.x, va.y, h0, l0);
            split2(va.z, va.w, h1, l1);
            *(uint2*)&SA[nxt][kh][0][am * 24 + ak] = make_uint2(h0, h1);
            *(uint2*)&SA[nxt][kh][1][am * 24 + ak] = make_uint2(l0, l1);
            *(uint4*)&SB[nxt][kh][0][bm * 24 + bk] = vbh;
            *(uint4*)&SB[nxt][kh][1][bm * 24 + bk] = vbl;
            if (t7 < 16) {
                *(uint4*)&SB[nxt][kh][0][(64 + bm) * 24 + bk] = vsh;
                *(uint4*)&SB[nxt][kh][1][(64 + bm) * 24 + bk] = vsl;
            }
        }
        __syncthreads();
    }

    // cross-wk reduction: wk=1 dumps partials, wk=0 accumulates
    if (wk == 1) {
        int w = wm * 2 + wn;
        #pragma unroll
        for (int nf = 0; nf < 4; nf++)
            #pragma unroll
            for (int q = 0; q < 4; q++)
                SR[w][lane][nf * 4 + q] = c[nf][q];
        if (wn == 0) {
            #pragma unroll
            for (int q = 0; q < 4; q++) SR[w][lane][16 + q] = csp[q];
        }
    }
    __syncthreads();

    if (wk == 0) {
        int w = wm * 2 + wn;
        #pragma unroll
        for (int nf = 0; nf < 4; nf++)
            #pragma unroll
            for (int q = 0; q < 4; q++)
                c[nf][q] += SR[w][lane][nf * 4 + q];
        if (wn == 0) {
            #pragma unroll
            for (int q = 0; q < 4; q++) csp[q] += SR[w][lane][16 + q];
        }

        // write xo tile (acc + pre) to smem
        const float* pre = g_pre + (size_t)t * BB * NPAD;
        int r0 = wm * 16 + g;
        int r1 = r0 + 8;
        #pragma unroll
        for (int nf = 0; nf < 4; nf++) {
            int cc = wn * 32 + nf * 8 + 2 * tq;
            const float* p0 = &pre[(size_t)(m0 + r0) * NPAD + n0 + cc];
            const float* p1 = &pre[(size_t)(m0 + r1) * NPAD + n0 + cc];
            SX[r0 * 76 + cc]     = c[nf][0] + p0[0];
            SX[r0 * 76 + cc + 1] = c[nf][1] + p0[1];
            SX[r1 * 76 + cc]     = c[nf][2] + p1[0];
            SX[r1 * 76 + cc + 1] = c[nf][3] + p1[1];
        }
        if (wn == 0) {
            int cc = 64 + 2 * tq;
            const float* p0 = &pre[(size_t)(m0 + r0) * NPAD + 1536 + 2 * tq];
            const float* p1 = &pre[(size_t)(m0 + r1) * NPAD + 1536 + 2 * tq];
            SX[r0 * 76 + cc]     = csp[0] + p0[0];
            SX[r0 * 76 + cc + 1] = csp[1] + p0[1];
            SX[r1 * 76 + cc]     = csp[2] + p1[0];
            SX[r1 * 76 + cc + 1] = csp[3] + p1[1];
        }
    }
    __syncthreads();

    // per-row cumax softmax from special cols (threads 0..31)
    if (tid < 32) {
        int row = tid;
        float a0 = SX[row * 76 + 64], a1 = SX[row * 76 + 65], a2 = SX[row * 76 + 66];
        float m = fmaxf(a0, fmaxf(a1, a2));
        float e0v = expf(a0 - m), e1v = expf(a1 - m), e2v = expf(a2 - m);
        float inv = 1.f / (e0v + e1v + e2v);
        float fm0 = e0v * inv, fm1 = (e0v + e1v) * inv, fm2 = (e0v + e1v + e2v) * inv;
        float b0 = SX[row * 76 + 67], b1 = SX[row * 76 + 68], b2 = SX[row * 76 + 69];
        float mb = fmaxf(b0, fmaxf(b1, b2));
        float f0 = expf(b0 - mb), f1 = expf(b1 - mb), f2 = expf(b2 - mb);
        float invb = 1.f / (f0 + f1 + f2);
        float im0 = (f0 + f1 + f2) * invb, im1 = (f1 + f2) * invb, im2 = f2 * invb;
        int l = e0 >> 7;
        sfm[row] = (l == 0) ? fm0 : ((l == 1) ? fm1 : fm2);
        sim[row] = (l == 0) ? im0 : ((l == 1) ? im1 : im2);
        if (blockIdx.x == 0)
            g_dish[t * BB + m0 + row] = 1.f - (fm0 + fm1 + fm2) * (1.f / 3.f);
    }
    __syncthreads();

    // in-block pointwise for 32 rows x 16 elements (256 threads, 2 iters)
    #pragma unroll
    for (int i = 0; i < 2; i++) {
        int idx = tid + i * 256;
        int row = idx >> 4;
        int le = idx & 15;
        int ge = e0 + le;
        int p = m0 + row;
        const float* x4 = &SX[row * 76 + le * 4];
        float fg = sigm(x4[0]);
        float ig = sigm(x4[1]);
        float og = sigm(x4[2]);
        float ci = tanhf(x4[3]);
        float fm = sfm[row], im = sim[row], ov = fm * im;
        float cl = g_c[p * HH + ge];
        float cn = ov * (fg * cl + ig * ci) + (fm - ov) * cl + (im - ov) * ci;
        float hn = og * tanhf(cn);
        g_c[p * HH + ge] = cn;
        Hout[p * HH + ge] = hn;
        g_hist[((size_t)t * BB + p) * HH + ge] = hn;
    }
}

// ---------------- batched epilogue ----------------
__global__ void k_fin1(const float* __restrict__ scale_w, const float* __restrict__ scale_b,
                       const float* __restrict__ rescale_w, const float* __restrict__ rescale_b) {
    int p = blockIdx.x;
    int tl = g_vlen[p] - 1;
    int tid = threadIdx.x;
    __shared__ float s_ldis[KW];
    __shared__ float s_th[HH];
    __shared__ float s_r1[HID];

    if (tid == 0) {
        float buf[KW];
        float cs = 0.f;
        #pragma unroll
        for (int k = 0; k < KW; k++) {
            int s = tl - (KW - 1) + k;
            cs += (s >= 0) ? g_dish[s * BB + p] : 0.f;
            buf[k] = cs;
        }
        float m = buf[0];
        #pragma unroll
        for (int k = 1; k < KW; k++) m = fmaxf(m, buf[k]);
        float sum = 0.f;
        #pragma unroll
        for (int k = 0; k < KW; k++) { buf[k] = expf(buf[k] - m); sum += buf[k]; }
        float invs = 1.f / sum;
        #pragma unroll
        for (int k = 0; k < KW; k++) s_ldis[k] = buf[k] * invs;
    }
    __syncthreads();

    for (int e = tid; e < HH; e += 256) {
        float tp = 0.f;
        #pragma unroll
        for (int k = 0; k < KW; k++) {
            int s = tl - (KW - 1) + k;
            float hv = (s >= 0) ? g_hist[((size_t)s * BB + p) * HH + e] : 0.f;
            float lv = hv * s_ldis[k];
            g_lh[(size_t)p * CONVK + e * KW + k] = lv;
            tp += lv;
        }
        s_th[e] = tp * (1.f / KW);
    }
    __syncthreads();

    if (tid < HID) {
        float a = scale_b[tid];
        for (int h = 0; h < HH; h++) a += s_th[h] * scale_w[h * HID + tid];
        s_r1[tid] = fmaxf(a, 0.f);
    }
    __syncthreads();

    for (int e = tid; e < HH; e += 256) {
        float th2 = rescale_b[e];
        #pragma unroll 8
        for (int j = 0; j < HID; j++) th2 += s_r1[j] * rescale_w[j * HH + e];
        g_theme[p * HH + e] = sigm(th2);
    }
}

// fin2: conv GEMM  g_conv[512,384] = g_lh[512,3840] @ g_convT[3840,384]
__global__ void k_fin2() {
    __shared__ float As[16][68];
    __shared__ float Bs[16][68];
    int m0 = blockIdx.y * 64;
    int nb = blockIdx.x * 64;
    int tid  = threadIdx.x;
    int ty   = tid >> 4, tx = tid & 15;
    int arow = tid >> 2, akk = (tid & 3) << 2;
    int bk   = tid >> 4, bn  = (tid & 15) << 2;
    float acc[4][4] = {};
    const float* A = g_lh + (size_t)m0 * CONVK;

    float4 a_nxt = *(const float4*)(A + (size_t)arow * CONVK + akk);
    float4 b_nxt = *(const float4*)(g_convT + bk * HH + nb + bn);

    for (int k0 = 0; k0 < CONVK; k0 += 16) {
        As[akk + 0][arow] = a_nxt.x; As[akk + 1][arow] = a_nxt.y;
        As[akk + 2][arow] = a_nxt.z; As[akk + 3][arow] = a_nxt.w;
        *(float4*)&Bs[bk][bn] = b_nxt;
        __syncthreads();
        if (k0 + 16 < CONVK) {
            a_nxt = *(const float4*)(A + (size_t)arow * CONVK + k0 + 16 + akk);
            b_nxt = *(const float4*)(g_convT + (k0 + 16 + bk) * HH + nb + bn);
        }
        #pragma unroll
        for (int k = 0; k < 16; k++) {
            float4 a = *(const float4*)&As[k][ty * 4];
            float4 b = *(const float4*)&Bs[k][tx * 4];
            float avr[4] = {a.x, a.y, a.z, a.w};
            float bvr[4] = {b.x, b.y, b.z, b.w};
            #pragma unroll
            for (int i = 0; i < 4; i++)
                #pragma unroll
                for (int j = 0; j < 4; j++) acc[i][j] += avr[i] * bvr[j];
        }
        __syncthreads();
    }
    #pragma unroll
    for (int i = 0; i < 4; i++)
        #pragma unroll
        for (int j = 0; j < 4; j++)
            g_conv[(m0 + ty * 4 + i) * HH + nb + tx * 4 + j] = acc[i][j];
}

__global__ void k_fin3(const float* __restrict__ conv_b, const float* __restrict__ out_w,
                       const float* __restrict__ out_b, float* __restrict__ out) {
    int p = blockIdx.x;
    int tid = threadIdx.x;
    int tl = g_vlen[p] - 1;
    __shared__ float s_rnn[HH];
    s_rnn[tid] = g_theme[p * HH + tid] * (g_conv[p * HH + tid] + conv_b[tid])
               + g_hist[((size_t)tl * BB + p) * HH + tid];
    __syncthreads();
    if (tid < LAB) {
        float a = out_b[tid];
        for (int h = 0; h < HH; h++) a += s_rnn[h] * out_w[h * LAB + tid];
        out[g_perm[p] * LAB + tid] = a;
    }
}

// ---------------- launch ----------------
extern "C" void kernel_launch(void* const* d_in, const int* in_sizes, int n_in,
                              void* d_out, int out_size) {
    const float* X         = (const float*)d_in[0];
    const int*   vlen      = (const int*)  d_in[1];
    const float* kw        = (const float*)d_in[2];
    const float* kb        = (const float*)d_in[3];
    const float* rw        = (const float*)d_in[4];
    const float* rb        = (const float*)d_in[5];
    const float* scale_w   = (const float*)d_in[6];
    const float* scale_b   = (const float*)d_in[7];
    const float* rescale_w = (const float*)d_in[8];
    const float* rescale_b = (const float*)d_in[9];
    const float* conv_w    = (const float*)d_in[10];
    const float* conv_b    = (const float*)d_in[11];
    const float* out_w     = (const float*)d_in[12];
    const float* out_b     = (const float*)d_in[13];
    float* out = (float*)d_out;

    k_setup<<<1, 1>>>(vlen);
    k_rows<<<BB, 128>>>();
    k_zero<<<(BB * HH + 255) / 256, 256>>>();
    k_convT<<<(HH * HH * KW + 255) / 256, 256>>>(conv_w);
    k_prep<<<NPAD, 384>>>(kw, kb, rw, rb);

    k_gemm_pre_fp16<<<dim3(13, 1024), 256>>>(X);

    for (int t = 0; t < TT; t++) {
        k_step<<<dim3(24, 16), 256>>>(t);
    }

    k_fin1<<<BB, 256>>>(scale_w, scale_b, rescale_w, rescale_b);
    k_fin2<<<dim3(HH / 64, BB / 64), 256>>>();
    k_fin3<<<BB, HH>>>(conv_b, out_w, out_b, out);
}